// round 14
// baseline (speedup 1.0000x reference)
#include <cuda_runtime.h>
#include <cstdint>

// Problem constants
#define BATCHN 128
#define GS 7
#define NB 2
#define NC 20
#define CH 30
#define CELLS (BATCHN * GS * GS)      // 6272
#define NTOT (CELLS * NB)             // 12544
#define PER_BATCH (GS * GS * NB)      // 98
#define THR_NMS 0.3f

#define NBUCK 4096
#define BSHIFT 11                     // 23-bit window >> 11 -> 12-bit bucket

typedef unsigned long long u64;

// ---------------- device scratch (static; no cudaMalloc) ---------------------
__device__ __align__(16) u64 g_vkeys[NTOT];     // compacted valid keys
__device__ __align__(16) u64 g_bsorted[NTOT];   // bucket-grouped valid keys
__device__ u64 g_keyfull[NTOT];                 // per-slot key (valid slots only)
__device__ float4 g_box[NTOT];
__device__ float4 g_pay[NTOT];        // (score, label, keep, 0)
__device__ int g_cnt[BATCHN];         // valid count per batch
__device__ u64 g_vmask[BATCHN * 2];   // validity bitmask per batch (98 bits)
__device__ __align__(16) unsigned g_hist[NBUCK];   // zeroed by scan kernel
__device__ unsigned g_prefix[NBUCK + 1];
// self-cleaning compaction counter: kernel A adds; scan kernel resets to 0.
__device__ int g_vtotal;

// sigmoid matching XLA-GPU exp-based logistic: 1/(1+__nv_expf(-x)), div.rn
__device__ __forceinline__ float sigmoidf(float x) {
    return 1.0f / (1.0f + expf(-x));
}

__device__ __forceinline__ unsigned f2sortable(float f) {
    unsigned b = __float_as_uint(f);
    return (b & 0x80000000u) ? ~b : (b | 0x80000000u);
}

// valid hi-words lie in (0xBF000000, 0xBF800000]  (conf in (0.5, 1.0])
__device__ __forceinline__ unsigned bucket_of(unsigned hi) {
    unsigned d = (hi - 0xBF000000u) >> BSHIFT;
    return min(d, (unsigned)(NBUCK - 1));
}

// ============ A) fused decode + parallel local rank + NMS + compaction =======
__global__ void __launch_bounds__(256) decode_nms_kernel(const float* __restrict__ p) {
    __shared__ float s_dec[GS * GS * CH];        // 1470 decoded values
    __shared__ u64 s_key[PER_BATCH];
    __shared__ float4 s_nbox[PER_BATCH];
    __shared__ unsigned char s_nlab[PER_BATCH];
    __shared__ unsigned char s_nloc[PER_BATCH];
    __shared__ unsigned char s_keep[PER_BATCH];
    __shared__ __align__(16) unsigned s_adj[PER_BATCH][4];  // suppression rows
    __shared__ unsigned s_supw[4];
    __shared__ unsigned s_wb[4];
    __shared__ int s_cnt;
    __shared__ int s_base;

    int tid = threadIdx.x;
    int b = blockIdx.x;

    // Phase 0: cooperative sigmoid decode (w,h channels raw)
    const float* pb = p + (size_t)b * (GS * GS * CH);
    for (int i = tid; i < GS * GS * CH; i += 256) {
        int c = i % CH;
        float x = pb[i];
        bool raw = (c == 2) | (c == 3) | (c == 6) | (c == 7);
        s_dec[i] = raw ? x : sigmoidf(x);
    }
    if (tid < PER_BATCH) {
        s_adj[tid][0] = 0; s_adj[tid][1] = 0; s_adj[tid][2] = 0; s_adj[tid][3] = 0;
        s_keep[tid] = 0;
    }
    __syncthreads();

    // Phase 1: per-box decode (one thread per box)
    bool valid = false;
    u64 mykey = 0;
    float4 mybox;
    float myconf = 0.0f;
    unsigned char mylab = 0;
    if (tid < PER_BATCH) {
        int cell = tid >> 1;
        int bb = tid & 1;
        int gy = cell / GS, gx = cell % GS;
        const float* d = s_dec + cell * CH;

        float best = d[8 + NB + 0];
        int bi = 0;
#pragma unroll
        for (int c = 1; c < NC; c++) {
            float v = d[8 + NB + c];
            if (v > best) { best = v; bi = c; }
        }
        mylab = (unsigned char)(bi + 1);

        myconf = d[8 + bb];
        valid = myconf > 0.5f;
        float sx = d[bb * 4 + 0];
        float sy = d[bb * 4 + 1];
        float w = d[bb * 4 + 2];
        float h = d[bb * 4 + 3];
        float cx = (sx + (float)gx) / 7.0f;
        float cy = (sy + (float)gy) / 7.0f;
        mybox.x = cx - w / 2.0f;
        mybox.y = cy - h / 2.0f;
        mybox.z = cx + w / 2.0f;
        mybox.w = cy + h / 2.0f;

        int n = b * PER_BATCH + tid;
        g_box[n] = mybox;
        float keyf = valid ? myconf : __int_as_float(0xff800000);   // -inf
        mykey = ((u64)f2sortable(keyf) << 32) | (unsigned)n;
        s_key[tid] = mykey;
        if (valid) {
            g_keyfull[n] = mykey;
            atomicAdd(&g_hist[bucket_of((unsigned)(mykey >> 32))], 1u);
        }
    }
    unsigned wb = __ballot_sync(0xffffffffu, valid);
    if ((tid & 31) == 0 && tid < 128) s_wb[tid >> 5] = wb;
    __syncthreads();
    if (tid == 0) {
        u64 m0 = (u64)s_wb[0] | ((u64)s_wb[1] << 32);
        u64 m1 = (u64)s_wb[2] | ((u64)s_wb[3] << 32);
        g_vmask[2 * b] = m0;
        g_vmask[2 * b + 1] = m1;
        int cnt = __popcll(m0) + __popcll(m1);
        s_cnt = cnt;
        g_cnt[b] = cnt;
        s_base = atomicAdd(&g_vtotal, cnt);
    }
    __syncthreads();

    // Phase 2: parallel local rank (valid keys outrank all invalid; keys unique)
    if (tid < PER_BATCH && valid) {
        int r = 0;
#pragma unroll 7
        for (int j = 0; j < PER_BATCH; j++)
            r += (s_key[j] > mykey);
        s_nbox[r] = mybox;
        s_nlab[r] = mylab;
        s_nloc[r] = (unsigned char)tid;
        g_vkeys[s_base + r] = mykey;
    }
    __syncthreads();

    int cnt = s_cnt;

    // Phase 3: flattened triangular pairwise IoU -> adjacency bits
    {
        int P = cnt * (cnt - 1) / 2;
        for (int pp = tid; pp < P; pp += 256) {
            int s = P - 1 - pp;
            int k = (int)floorf((sqrtf(8.0f * (float)s + 1.0f) - 1.0f) * 0.5f);
            while ((k + 1) * (k + 2) / 2 <= s) k++;
            while (k * (k + 1) / 2 > s) k--;
            int o = s - k * (k + 1) / 2;
            int i = cnt - 2 - k;
            int j = cnt - 1 - o;
            if (s_nlab[i] == s_nlab[j]) {
                float4 bi = s_nbox[i];
                float4 bj = s_nbox[j];
                float ltx = fmaxf(bi.x, bj.x);
                float lty = fmaxf(bi.y, bj.y);
                float rbx = fminf(bi.z, bj.z);
                float rby = fminf(bi.w, bj.w);
                float iw = fmaxf(rbx - ltx, 0.0f);
                float ih = fmaxf(rby - lty, 0.0f);
                float inter = iw * ih;
                float ai = (bi.z - bi.x) * (bi.w - bi.y);
                float aj = (bj.z - bj.x) * (bj.w - bj.y);
                float uni = ai + aj - inter;
                float iou = inter / fmaxf(uni, 1e-9f);
                if (iou > THR_NMS)
                    atomicOr(&s_adj[i][j >> 5], 1u << (j & 31));
            }
        }
    }
    __syncthreads();

    // Phase 4: greedy scan, warp-parallel, branch-free mask accumulation
    if (tid < 32) {
        int lane = tid;
        unsigned r00 = s_adj[lane][0],      r01 = s_adj[lane][1];
        unsigned r02 = s_adj[lane][2],      r03 = s_adj[lane][3];
        unsigned r10 = s_adj[lane + 32][0], r11 = s_adj[lane + 32][1];
        unsigned r12 = s_adj[lane + 32][2], r13 = s_adj[lane + 32][3];
        unsigned r20 = s_adj[lane + 64][0], r21 = s_adj[lane + 64][1];
        unsigned r22 = s_adj[lane + 64][2], r23 = s_adj[lane + 64][3];
        unsigned r30 = 0, r31 = 0, r32 = 0, r33 = 0;
        if (lane < 2) {
            r30 = s_adj[lane + 96][0]; r31 = s_adj[lane + 96][1];
            r32 = s_adj[lane + 96][2]; r33 = s_adj[lane + 96][3];
        }

        unsigned sup0 = 0, sup1 = 0, sup2 = 0, sup3 = 0;
        int c = cnt;
        int e0 = min(c, 32);
        for (int s = 0; s < e0; s++) {
            unsigned m = ((sup0 >> s) & 1u) - 1u;      // ~0 if kept, 0 if suppressed
            sup0 |= __shfl_sync(0xffffffffu, r00, s) & m;
            sup1 |= __shfl_sync(0xffffffffu, r01, s) & m;
            sup2 |= __shfl_sync(0xffffffffu, r02, s) & m;
            sup3 |= __shfl_sync(0xffffffffu, r03, s) & m;
        }
        int e1 = min(c - 32, 32);
        for (int s = 0; s < e1; s++) {
            unsigned m = ((sup1 >> s) & 1u) - 1u;
            sup0 |= __shfl_sync(0xffffffffu, r10, s) & m;
            sup1 |= __shfl_sync(0xffffffffu, r11, s) & m;
            sup2 |= __shfl_sync(0xffffffffu, r12, s) & m;
            sup3 |= __shfl_sync(0xffffffffu, r13, s) & m;
        }
        int e2 = min(c - 64, 32);
        for (int s = 0; s < e2; s++) {
            unsigned m = ((sup2 >> s) & 1u) - 1u;
            sup0 |= __shfl_sync(0xffffffffu, r20, s) & m;
            sup1 |= __shfl_sync(0xffffffffu, r21, s) & m;
            sup2 |= __shfl_sync(0xffffffffu, r22, s) & m;
            sup3 |= __shfl_sync(0xffffffffu, r23, s) & m;
        }
        int e3 = min(c - 96, 32);
        for (int s = 0; s < e3; s++) {
            unsigned m = ((sup3 >> s) & 1u) - 1u;
            sup0 |= __shfl_sync(0xffffffffu, r30, s) & m;
            sup1 |= __shfl_sync(0xffffffffu, r31, s) & m;
            sup2 |= __shfl_sync(0xffffffffu, r32, s) & m;
            sup3 |= __shfl_sync(0xffffffffu, r33, s) & m;
        }
        if (lane == 0) {
            s_supw[0] = sup0; s_supw[1] = sup1; s_supw[2] = sup2; s_supw[3] = sup3;
        }
    }
    __syncthreads();

    if (tid < cnt) {
        if (!((s_supw[tid >> 5] >> (tid & 31)) & 1u))
            s_keep[s_nloc[tid]] = 1;
    }
    __syncthreads();

    // Phase 5: payload write
    if (tid < PER_BATCH) {
        int n = b * PER_BATCH + tid;
        g_pay[n] = make_float4(myconf, (float)mylab,
                               s_keep[tid] ? 1.0f : 0.0f, 0.0f);
    }
}

// ============ B) single-block prefix-sum + bucket scatter ====================
__global__ void __launch_bounds__(1024) scan_scatter_kernel() {
    __shared__ unsigned s_p[NBUCK];     // running bucket offsets
    __shared__ unsigned s_wsum[32];
    __shared__ int s_V;
    int tid = threadIdx.x;
    int lane = tid & 31, wid = tid >> 5;
    unsigned base = tid * 4;

    uint4 h4 = *(const uint4*)&g_hist[base];
    unsigned t = h4.x + h4.y + h4.z + h4.w;
    *(uint4*)&g_hist[base] = make_uint4(0, 0, 0, 0);   // self-clean for next launch

    unsigned x = t;
#pragma unroll
    for (int d = 1; d < 32; d <<= 1) {
        unsigned y = __shfl_up_sync(0xffffffffu, x, d);
        if (lane >= d) x += y;
    }
    if (lane == 31) s_wsum[wid] = x;
    __syncthreads();
    if (tid < 32) {
        unsigned v = s_wsum[tid], xx = v;
#pragma unroll
        for (int d = 1; d < 32; d <<= 1) {
            unsigned y = __shfl_up_sync(0xffffffffu, xx, d);
            if (tid >= d) xx += y;
        }
        s_wsum[tid] = xx - v;               // exclusive warp offsets
    }
    __syncthreads();
    unsigned run = x - t + s_wsum[wid];     // exclusive prefix of this chunk
    s_p[base + 0] = run; g_prefix[base + 0] = run; run += h4.x;
    s_p[base + 1] = run; g_prefix[base + 1] = run; run += h4.y;
    s_p[base + 2] = run; g_prefix[base + 2] = run; run += h4.z;
    s_p[base + 3] = run; g_prefix[base + 3] = run; run += h4.w;
    if (tid == 1023) {
        g_prefix[NBUCK] = run;              // == V
        s_V = (int)run;
        g_vtotal = 0;                       // self-clean compaction counter
    }
    __syncthreads();

    int V = s_V;
    for (int i = tid; i < V; i += 1024) {
        u64 key = g_vkeys[i];
        unsigned bk = bucket_of((unsigned)(key >> 32));
        unsigned pos = atomicAdd(&s_p[bk], 1u);
        g_bsorted[pos] = key;
    }
}

// ============ C) per-element rank + output write =============================
__global__ void __launch_bounds__(256) write_kernel(float* __restrict__ out) {
    __shared__ int s_incl[BATCHN];
    __shared__ int s_ws[4];
    int tid = threadIdx.x, lane = tid & 31;

    if (tid < BATCHN) {
        int x = g_cnt[tid];
#pragma unroll
        for (int d = 1; d < 32; d <<= 1) {
            int y = __shfl_up_sync(0xffffffffu, x, d);
            if (lane >= d) x += y;
        }
        if (lane == 31) s_ws[tid >> 5] = x;
        s_incl[tid] = x;
    }
    __syncthreads();
    if (tid == 0) {
        int a = 0;
#pragma unroll
        for (int w = 0; w < 4; w++) { int t = s_ws[w]; s_ws[w] = a; a += t; }
    }
    __syncthreads();
    if (tid < BATCHN) s_incl[tid] += s_ws[tid >> 5];
    __syncthreads();

    int V = s_incl[BATCHN - 1];
    int n = blockIdx.x * 256 + tid;        // 49*256 == NTOT exactly
    int b = n / PER_BATCH;
    int local = n - b * PER_BATCH;
    u64 m0 = g_vmask[2 * b];
    u64 m1 = g_vmask[2 * b + 1];
    bool valid = (local < 64) ? ((m0 >> local) & 1ULL)
                              : ((m1 >> (local - 64)) & 1ULL);

    if (valid) {
        u64 key = g_keyfull[n];
        unsigned bk = bucket_of((unsigned)(key >> 32));
        unsigned lo = g_prefix[bk];
        unsigned hiE = g_prefix[bk + 1];
        int rank = V - (int)hiE;           // keys in strictly-higher buckets
        for (unsigned i = lo; i < hiE; i++)
            rank += (g_bsorted[i] > key);  // exact in-bucket (handles ties)
        float4 bx = g_box[n];
        float4 pay = g_pay[n];
        out[rank] = (float)b;
        *(float4*)(out + NTOT + 4 * rank) = bx;
        out[5 * NTOT + rank] = pay.y;      // label
        out[6 * NTOT + rank] = pay.x;      // score
        out[7 * NTOT + rank] = pay.z;      // keep
    } else {
        u64 i0 = ~m0;
        u64 i1 = (~m1) & ((1ULL << (PER_BATCH - 64)) - 1);
        int after;
        if (local < 64) {
            u64 hi = (local == 63) ? 0ULL : (i0 >> (local + 1));
            after = __popcll(hi) + __popcll(i1);
        } else {
            after = __popcll(i1 >> (local - 63));
        }
        int invafter = (NTOT - V) - (PER_BATCH * (b + 1) - s_incl[b]);
        int rank = V + invafter + after;

        float4 bx = g_box[n];
        float4 pay = g_pay[n];
        out[rank] = (float)b;
        *(float4*)(out + NTOT + 4 * rank) = bx;
        out[5 * NTOT + rank] = pay.y;
        out[6 * NTOT + rank] = pay.x;
        out[7 * NTOT + rank] = 0.0f;
    }
}

// ---------------- launch -----------------------------------------------------
extern "C" void kernel_launch(void* const* d_in, const int* in_sizes, int n_in,
                              void* d_out, int out_size) {
    const float* p = (const float*)d_in[0];
    float* out = (float*)d_out;

    decode_nms_kernel<<<BATCHN, 256>>>(p);
    scan_scatter_kernel<<<1, 1024>>>();
    write_kernel<<<NTOT / 256, 256>>>(out);
}

// round 15
// speedup vs baseline: 1.2763x; 1.2763x over previous
#include <cuda_runtime.h>
#include <cstdint>

// Problem constants
#define BATCHN 128
#define GS 7
#define NB 2
#define NC 20
#define CH 30
#define CELLS (BATCHN * GS * GS)      // 6272
#define NTOT (CELLS * NB)             // 12544
#define PER_BATCH (GS * GS * NB)      // 98
#define THR_NMS 0.3f

#define NBUCK 4096
#define BSHIFT 11                     // 23-bit score window >> 11 -> 12-bit bucket

typedef unsigned long long u64;

// ---------------- device scratch (static; no cudaMalloc) ---------------------
__device__ u64 g_keyfull[NTOT];       // per-slot key (valid slots only)
__device__ float4 g_box[NTOT];
__device__ float4 g_pay[NTOT];        // (score, label, keep, 0)
__device__ int g_cnt[BATCHN];         // valid count per batch
__device__ u64 g_vmask[BATCHN * 2];   // validity bitmask per batch (98 bits)
// fused memset region: [0..NBUCK) histogram, [NBUCK..2*NBUCK) chain heads
// (head stores n+1; 0 = empty)
__device__ __align__(16) unsigned g_tables[2 * NBUCK];
__device__ unsigned g_bnext[NTOT];    // chain next (same n+1 encoding)

// sigmoid matching XLA-GPU exp-based logistic: 1/(1+__nv_expf(-x)), div.rn
__device__ __forceinline__ float sigmoidf(float x) {
    return 1.0f / (1.0f + expf(-x));
}

__device__ __forceinline__ unsigned f2sortable(float f) {
    unsigned b = __float_as_uint(f);
    return (b & 0x80000000u) ? ~b : (b | 0x80000000u);
}

// valid hi-words lie in (0xBF000000, 0xBF800000]  (conf in (0.5, 1.0])
__device__ __forceinline__ unsigned bucket_of(unsigned hi) {
    unsigned d = (hi - 0xBF000000u) >> BSHIFT;
    return min(d, (unsigned)(NBUCK - 1));
}

// ============ A) fused decode + per-batch local rank + NMS ===================
__global__ void __launch_bounds__(256) decode_nms_kernel(const float* __restrict__ p) {
    __shared__ float s_dec[GS * GS * CH];        // 1470 decoded values
    __shared__ u64 s_key[PER_BATCH];
    __shared__ float4 s_nbox[PER_BATCH];
    __shared__ unsigned char s_nlab[PER_BATCH];
    __shared__ unsigned char s_nloc[PER_BATCH];
    __shared__ unsigned char s_keep[PER_BATCH];
    __shared__ __align__(16) unsigned s_adj[PER_BATCH][4];  // suppression rows
    __shared__ unsigned s_supw[4];
    __shared__ unsigned s_wb[4];
    __shared__ int s_cnt;

    int tid = threadIdx.x;
    int b = blockIdx.x;

    // Phase 0: cooperative sigmoid decode (w,h channels raw)
    const float* pb = p + (size_t)b * (GS * GS * CH);
    for (int i = tid; i < GS * GS * CH; i += 256) {
        int c = i % CH;
        float x = pb[i];
        bool raw = (c == 2) | (c == 3) | (c == 6) | (c == 7);
        s_dec[i] = raw ? x : sigmoidf(x);
    }
    if (tid < PER_BATCH) {
        s_adj[tid][0] = 0; s_adj[tid][1] = 0; s_adj[tid][2] = 0; s_adj[tid][3] = 0;
        s_keep[tid] = 0;
    }
    __syncthreads();

    // Phase 1: per-box decode (one thread per box)
    bool valid = false;
    u64 mykey = 0;
    float4 mybox;
    float myconf = 0.0f;
    unsigned char mylab = 0;
    if (tid < PER_BATCH) {
        int cell = tid >> 1;
        int bb = tid & 1;
        int gy = cell / GS, gx = cell % GS;
        const float* d = s_dec + cell * CH;

        float best = d[8 + NB + 0];
        int bi = 0;
#pragma unroll
        for (int c = 1; c < NC; c++) {
            float v = d[8 + NB + c];
            if (v > best) { best = v; bi = c; }
        }
        mylab = (unsigned char)(bi + 1);

        myconf = d[8 + bb];
        valid = myconf > 0.5f;
        float sx = d[bb * 4 + 0];
        float sy = d[bb * 4 + 1];
        float w = d[bb * 4 + 2];
        float h = d[bb * 4 + 3];
        float cx = (sx + (float)gx) / 7.0f;
        float cy = (sy + (float)gy) / 7.0f;
        mybox.x = cx - w / 2.0f;
        mybox.y = cy - h / 2.0f;
        mybox.z = cx + w / 2.0f;
        mybox.w = cy + h / 2.0f;

        int n = b * PER_BATCH + tid;
        g_box[n] = mybox;
        float keyf = valid ? myconf : __int_as_float(0xff800000);   // -inf
        mykey = ((u64)f2sortable(keyf) << 32) | (unsigned)n;
        s_key[tid] = mykey;
        if (valid) {
            g_keyfull[n] = mykey;
            unsigned bk = bucket_of((unsigned)(mykey >> 32));
            atomicAdd(&g_tables[bk], 1u);                      // histogram
            unsigned old = atomicExch(&g_tables[NBUCK + bk], (unsigned)(n + 1));
            g_bnext[n] = old;                                  // chain link
        }
    }
    unsigned wb = __ballot_sync(0xffffffffu, valid);
    if ((tid & 31) == 0 && tid < 128) s_wb[tid >> 5] = wb;
    __syncthreads();
    if (tid == 0) {
        u64 m0 = (u64)s_wb[0] | ((u64)s_wb[1] << 32);
        u64 m1 = (u64)s_wb[2] | ((u64)s_wb[3] << 32);
        g_vmask[2 * b] = m0;
        g_vmask[2 * b + 1] = m1;
        int cnt = __popcll(m0) + __popcll(m1);
        s_cnt = cnt;
        g_cnt[b] = cnt;
    }
    __syncthreads();

    // Phase 2: parallel local rank (for NMS score ordering within the batch)
    if (tid < PER_BATCH && valid) {
        int r = 0;
#pragma unroll 7
        for (int j = 0; j < PER_BATCH; j++)
            r += (s_key[j] > mykey);
        s_nbox[r] = mybox;
        s_nlab[r] = mylab;
        s_nloc[r] = (unsigned char)tid;
    }
    __syncthreads();

    int cnt = s_cnt;

    // Phase 3: flattened triangular pairwise IoU -> adjacency bits
    {
        int P = cnt * (cnt - 1) / 2;
        for (int pp = tid; pp < P; pp += 256) {
            int s = P - 1 - pp;
            int k = (int)floorf((sqrtf(8.0f * (float)s + 1.0f) - 1.0f) * 0.5f);
            while ((k + 1) * (k + 2) / 2 <= s) k++;
            while (k * (k + 1) / 2 > s) k--;
            int o = s - k * (k + 1) / 2;
            int i = cnt - 2 - k;
            int j = cnt - 1 - o;
            if (s_nlab[i] == s_nlab[j]) {
                float4 bi = s_nbox[i];
                float4 bj = s_nbox[j];
                float ltx = fmaxf(bi.x, bj.x);
                float lty = fmaxf(bi.y, bj.y);
                float rbx = fminf(bi.z, bj.z);
                float rby = fminf(bi.w, bj.w);
                float iw = fmaxf(rbx - ltx, 0.0f);
                float ih = fmaxf(rby - lty, 0.0f);
                float inter = iw * ih;
                float ai = (bi.z - bi.x) * (bi.w - bi.y);
                float aj = (bj.z - bj.x) * (bj.w - bj.y);
                float uni = ai + aj - inter;
                float iou = inter / fmaxf(uni, 1e-9f);
                if (iou > THR_NMS)
                    atomicOr(&s_adj[i][j >> 5], 1u << (j & 31));
            }
        }
    }
    __syncthreads();

    // Phase 4: greedy scan, warp-parallel, branch-free mask accumulation
    if (tid < 32) {
        int lane = tid;
        unsigned r00 = s_adj[lane][0],      r01 = s_adj[lane][1];
        unsigned r02 = s_adj[lane][2],      r03 = s_adj[lane][3];
        unsigned r10 = s_adj[lane + 32][0], r11 = s_adj[lane + 32][1];
        unsigned r12 = s_adj[lane + 32][2], r13 = s_adj[lane + 32][3];
        unsigned r20 = s_adj[lane + 64][0], r21 = s_adj[lane + 64][1];
        unsigned r22 = s_adj[lane + 64][2], r23 = s_adj[lane + 64][3];
        unsigned r30 = 0, r31 = 0, r32 = 0, r33 = 0;
        if (lane < 2) {
            r30 = s_adj[lane + 96][0]; r31 = s_adj[lane + 96][1];
            r32 = s_adj[lane + 96][2]; r33 = s_adj[lane + 96][3];
        }

        unsigned sup0 = 0, sup1 = 0, sup2 = 0, sup3 = 0;
        int c = cnt;
        int e0 = min(c, 32);
        for (int s = 0; s < e0; s++) {
            unsigned m = ((sup0 >> s) & 1u) - 1u;      // ~0 if kept, 0 if suppressed
            sup0 |= __shfl_sync(0xffffffffu, r00, s) & m;
            sup1 |= __shfl_sync(0xffffffffu, r01, s) & m;
            sup2 |= __shfl_sync(0xffffffffu, r02, s) & m;
            sup3 |= __shfl_sync(0xffffffffu, r03, s) & m;
        }
        int e1 = min(c - 32, 32);
        for (int s = 0; s < e1; s++) {
            unsigned m = ((sup1 >> s) & 1u) - 1u;
            sup0 |= __shfl_sync(0xffffffffu, r10, s) & m;
            sup1 |= __shfl_sync(0xffffffffu, r11, s) & m;
            sup2 |= __shfl_sync(0xffffffffu, r12, s) & m;
            sup3 |= __shfl_sync(0xffffffffu, r13, s) & m;
        }
        int e2 = min(c - 64, 32);
        for (int s = 0; s < e2; s++) {
            unsigned m = ((sup2 >> s) & 1u) - 1u;
            sup0 |= __shfl_sync(0xffffffffu, r20, s) & m;
            sup1 |= __shfl_sync(0xffffffffu, r21, s) & m;
            sup2 |= __shfl_sync(0xffffffffu, r22, s) & m;
            sup3 |= __shfl_sync(0xffffffffu, r23, s) & m;
        }
        int e3 = min(c - 96, 32);
        for (int s = 0; s < e3; s++) {
            unsigned m = ((sup3 >> s) & 1u) - 1u;
            sup0 |= __shfl_sync(0xffffffffu, r30, s) & m;
            sup1 |= __shfl_sync(0xffffffffu, r31, s) & m;
            sup2 |= __shfl_sync(0xffffffffu, r32, s) & m;
            sup3 |= __shfl_sync(0xffffffffu, r33, s) & m;
        }
        if (lane == 0) {
            s_supw[0] = sup0; s_supw[1] = sup1; s_supw[2] = sup2; s_supw[3] = sup3;
        }
    }
    __syncthreads();

    if (tid < cnt) {
        if (!((s_supw[tid >> 5] >> (tid & 31)) & 1u))
            s_keep[s_nloc[tid]] = 1;
    }
    __syncthreads();

    // Phase 5: payload write
    if (tid < PER_BATCH) {
        int n = b * PER_BATCH + tid;
        g_pay[n] = make_float4(myconf, (float)mylab,
                               s_keep[tid] ? 1.0f : 0.0f, 0.0f);
    }
}

// ============ B) per-element rank (bucket prefix + chain ties) + write =======
__global__ void __launch_bounds__(256) write_kernel(float* __restrict__ out) {
    __shared__ int s_pref[NBUCK];     // inclusive bucket prefix (16 KB)
    __shared__ int s_incl[BATCHN];
    __shared__ int s_ws[8];
    int tid = threadIdx.x, lane = tid & 31, wid = tid >> 5;

    // -- per-block redundant inclusive prefix over the 4096-bucket histogram --
    unsigned base = tid * 16;
    uint4 h0 = *(const uint4*)&g_tables[base + 0];
    uint4 h1 = *(const uint4*)&g_tables[base + 4];
    uint4 h2 = *(const uint4*)&g_tables[base + 8];
    uint4 h3 = *(const uint4*)&g_tables[base + 12];
    unsigned l[16] = { h0.x, h0.y, h0.z, h0.w, h1.x, h1.y, h1.z, h1.w,
                       h2.x, h2.y, h2.z, h2.w, h3.x, h3.y, h3.z, h3.w };
    unsigned tot = 0;
#pragma unroll
    for (int i = 0; i < 16; i++) { tot += l[i]; l[i] = tot; }  // local inclusive
    unsigned x = tot;
#pragma unroll
    for (int d = 1; d < 32; d <<= 1) {
        unsigned y = __shfl_up_sync(0xffffffffu, x, d);
        if (lane >= d) x += y;
    }
    if (lane == 31) s_ws[wid] = (int)x;
    __syncthreads();
    if (tid < 8) {
        int v = s_ws[tid], xx = v;
#pragma unroll
        for (int d = 1; d < 8; d <<= 1) {
            int y = __shfl_up_sync(0xffu, xx, d);
            if (tid >= d) xx += y;
        }
        s_ws[tid] = xx - v;               // exclusive warp offsets
    }
    __syncthreads();
    unsigned off = x - tot + (unsigned)s_ws[wid];   // exclusive prefix of chunk
#pragma unroll
    for (int i = 0; i < 16; i++) s_pref[base + i] = (int)(l[i] + off);

    // -- per-batch inclusive scan of valid counts (for invalid ranks) --
    if (tid < BATCHN) {
        int v = g_cnt[tid];
#pragma unroll
        for (int d = 1; d < 32; d <<= 1) {
            int y = __shfl_up_sync(0xffffffffu, v, d);
            if (lane >= d) v += y;
        }
        if (lane == 31) s_ws[4 + (tid >> 5)] = v;   // reuse slots 4..7
        s_incl[tid] = v;
    }
    __syncthreads();
    if (tid == 0) {
        int a = 0;
#pragma unroll
        for (int w = 0; w < 4; w++) { int t = s_ws[4 + w]; s_ws[4 + w] = a; a += t; }
    }
    __syncthreads();
    if (tid < BATCHN) s_incl[tid] += s_ws[4 + (tid >> 5)];
    __syncthreads();

    int V = s_incl[BATCHN - 1];

    int n = blockIdx.x * 256 + tid;       // 49*256 == NTOT exactly
    int b = n / PER_BATCH;
    int local = n - b * PER_BATCH;
    u64 m0 = g_vmask[2 * b];
    u64 m1 = g_vmask[2 * b + 1];
    bool valid = (local < 64) ? ((m0 >> local) & 1ULL)
                              : ((m1 >> (local - 64)) & 1ULL);

    if (valid) {
        u64 key = g_keyfull[n];
        unsigned bk = bucket_of((unsigned)(key >> 32));
        int rank = V - s_pref[bk];        // keys in strictly-higher buckets
        // in-bucket exact compares via chain walk (expected length ~1.5)
        unsigned cur = g_tables[NBUCK + bk];
        while (cur != 0) {
            int j = (int)cur - 1;
            if (j != n) rank += (g_keyfull[j] > key);
            cur = g_bnext[j];
        }
        float4 bx = g_box[n];
        float4 pay = g_pay[n];
        out[rank] = (float)b;
        *(float4*)(out + NTOT + 4 * rank) = bx;
        out[5 * NTOT + rank] = pay.y;     // label
        out[6 * NTOT + rank] = pay.x;     // score
        out[7 * NTOT + rank] = pay.z;     // keep
    } else {
        u64 i0 = ~m0;
        u64 i1 = (~m1) & ((1ULL << (PER_BATCH - 64)) - 1);
        int after;
        if (local < 64) {
            u64 hi = (local == 63) ? 0ULL : (i0 >> (local + 1));
            after = __popcll(hi) + __popcll(i1);
        } else {
            after = __popcll(i1 >> (local - 63));
        }
        int invafter = (NTOT - V) - (PER_BATCH * (b + 1) - s_incl[b]);
        int rank = V + invafter + after;

        float4 bx = g_box[n];
        float4 pay = g_pay[n];
        out[rank] = (float)b;
        *(float4*)(out + NTOT + 4 * rank) = bx;
        out[5 * NTOT + rank] = pay.y;
        out[6 * NTOT + rank] = pay.x;
        out[7 * NTOT + rank] = 0.0f;
    }
}

// ---------------- launch -----------------------------------------------------
extern "C" void kernel_launch(void* const* d_in, const int* in_sizes, int n_in,
                              void* d_out, int out_size) {
    const float* p = (const float*)d_in[0];
    float* out = (float*)d_out;

    void* tbl = nullptr;
    cudaGetSymbolAddress(&tbl, g_tables);
    cudaMemsetAsync(tbl, 0, 2 * NBUCK * sizeof(unsigned));

    decode_nms_kernel<<<BATCHN, 256>>>(p);
    write_kernel<<<NTOT / 256, 256>>>(out);
}